// round 3
// baseline (speedup 1.0000x reference)
#include <cuda_runtime.h>
#include <math.h>

// Problem constants
#define HW    4096          // 64*64 latent positions
#define CC    320           // hidden channels
#define CX    768           // encoder channels
#define LKV   77            // encoder seq len
#define DH    40            // head dim
#define NHEAD 8
#define NBATCH 10           // attention batches (ehs[:-1])
#define NINST 8             // boxes
#define LATENT 64

// ---------------- scratch (device globals; allocation is banned) -------------
__device__ float g_Q[2 * HW * CC];        // 2 distinct hidden states projected
__device__ float g_K[NBATCH * LKV * CC];
__device__ float g_V[NBATCH * LKV * CC];
__device__ float g_attn[9 * HW * CC];     // attention out for batches 1..9
__device__ float g_final[2 * HW * CC];    // rows 0..4095: attn batch0; 4096..: weighted
__device__ float g_pw[9 * HW];            // phase weights
__device__ float g_bscale[HW];            // s/(s+eps) for bias term on fused rows

// ---------------- tiled SGEMM: C = A(MxK) @ B(KxN) [+ bias epilogue] ---------
// BM=BN=64, BK=16, 256 threads, 4x4 microtile. K % 16 == 0, N % 64 == 0.
__global__ __launch_bounds__(256) void sgemm_kernel(
    const float* __restrict__ A, const float* __restrict__ B, float* __restrict__ Cm,
    int M, int N, int K,
    const float* __restrict__ bias, const float* __restrict__ bscale, int mode)
{
    __shared__ float As[16][64 + 1];
    __shared__ float Bs[16][64];

    int tid = threadIdx.x;
    int row0 = blockIdx.y * 64;
    int col0 = blockIdx.x * 64;
    int ty = tid / 16, tx = tid % 16;

    int arow = tid >> 2;            // 0..63
    int acol = (tid & 3) * 4;       // 0,4,8,12
    int brow = tid >> 4;            // 0..15
    int bcol = (tid & 15) * 4;      // 0..60

    float acc[4][4];
#pragma unroll
    for (int i = 0; i < 4; i++)
#pragma unroll
        for (int j = 0; j < 4; j++) acc[i][j] = 0.0f;

    for (int k0 = 0; k0 < K; k0 += 16) {
        float4 a4 = make_float4(0.f, 0.f, 0.f, 0.f);
        if (row0 + arow < M)
            a4 = *reinterpret_cast<const float4*>(&A[(size_t)(row0 + arow) * K + k0 + acol]);
        As[acol + 0][arow] = a4.x;
        As[acol + 1][arow] = a4.y;
        As[acol + 2][arow] = a4.z;
        As[acol + 3][arow] = a4.w;

        float4 b4 = *reinterpret_cast<const float4*>(&B[(size_t)(k0 + brow) * N + col0 + bcol]);
        *reinterpret_cast<float4*>(&Bs[brow][bcol]) = b4;
        __syncthreads();

#pragma unroll
        for (int k = 0; k < 16; ++k) {
            float ra[4], rb[4];
#pragma unroll
            for (int i = 0; i < 4; i++) ra[i] = As[k][ty * 4 + i];
#pragma unroll
            for (int j = 0; j < 4; j++) rb[j] = Bs[k][tx * 4 + j];
#pragma unroll
            for (int i = 0; i < 4; i++)
#pragma unroll
                for (int j = 0; j < 4; j++) acc[i][j] += ra[i] * rb[j];
        }
        __syncthreads();
    }

#pragma unroll
    for (int i = 0; i < 4; i++) {
        int row = row0 + ty * 4 + i;
        if (row >= M) continue;
#pragma unroll
        for (int j = 0; j < 4; j++) {
            int col = col0 + tx * 4 + j;
            float v = acc[i][j];
            if (mode == 1) {
                float bs = (row < HW) ? 1.0f : bscale[row - HW];
                v += bias[col] * bs;
            }
            Cm[(size_t)row * N + col] = v;
        }
    }
}

// ---------------- separable antialiased triangle resize weights --------------
// matches jax.image.resize bilinear (antialias=True), 512 -> 64, scale 1/8.
__device__ __forceinline__ float axis_weight(int o, float lo, float hi)
{
    float c = 8.0f * o + 3.5f;
    int j0 = 8 * o - 4;
    int j1 = 8 * o + 11;
    if (j0 < 0) j0 = 0;
    if (j1 > 511) j1 = 511;
    float wsum = 0.0f, win = 0.0f;
    for (int j = j0; j <= j1; ++j) {
        float w = 1.0f - fabsf((float)j - c) * 0.125f;
        wsum += w;
        float jf = (float)j;
        if (jf >= lo && jf < hi) win += w;
    }
    return win / wsum;
}

__global__ void mask_kernel(const float* __restrict__ bboxes, float* __restrict__ pw)
{
    int pos = blockIdx.x * 64 + threadIdx.x;   // 0..4095
    int y = pos >> 6;
    int x = pos & 63;
    pw[pos] = 0.1f;                            // row 0: constant phase
    for (int n = 0; n < NINST; ++n) {
        const float* bb = bboxes + n * 4;
        float wmin = floorf(512.0f * bb[0]);
        float hmin = floorf(512.0f * bb[1]);
        float wmax = floorf(512.0f * bb[2]);
        float hmax = floorf(512.0f * bb[3]);
        float fy = axis_weight(y, hmin, hmax);
        float fx = axis_weight(x, wmin, wmax);
        pw[(size_t)(n + 1) * HW + pos] = fy * fx * 10.0f;
    }
}

// ---------------- attention: one block per (b, h, 128-row q tile) ------------
__global__ __launch_bounds__(128) void attn_kernel(
    const float* __restrict__ Q, const float* __restrict__ K, const float* __restrict__ V,
    float* __restrict__ attn_out, float* __restrict__ final_in)
{
    __shared__ float Ks[LKV][DH];
    __shared__ float Vs[LKV][DH];
    __shared__ float Qs[128][DH];

    int qt = blockIdx.x;   // 0..31
    int h  = blockIdx.y;   // 0..7
    int b  = blockIdx.z;   // 0..9
    int tid = threadIdx.x; // 0..127

    const float* Kb = K + (size_t)b * LKV * CC + h * DH;
    const float* Vb = V + (size_t)b * LKV * CC + h * DH;
    for (int idx = tid; idx < LKV * DH; idx += 128) {
        int r = idx / DH, c = idx % DH;
        Ks[r][c] = Kb[(size_t)r * CC + c];
        Vs[r][c] = Vb[(size_t)r * CC + c];
    }
    int qb = (b == 0) ? 0 : 1;
    int q0 = qt * 128;
    const float* Qb = Q + ((size_t)qb * HW + q0) * CC + h * DH;
    for (int idx = tid; idx < 128 * DH; idx += 128) {
        int r = idx / DH, c = idx % DH;
        Qs[r][c] = Qb[(size_t)r * CC + c];
    }
    __syncthreads();

    float q[DH], acc[DH];
#pragma unroll
    for (int d = 0; d < DH; d++) { q[d] = Qs[tid][d]; acc[d] = 0.0f; }

    const float scale = 0.15811388300841897f;  // 1/sqrt(40)
    float l = 0.0f;

    for (int j = 0; j < LKV; ++j) {
        const float4* k4 = reinterpret_cast<const float4*>(&Ks[j][0]);
        float s = 0.0f;
#pragma unroll
        for (int d4 = 0; d4 < DH / 4; ++d4) {
            float4 kk = k4[d4];
            s += q[d4 * 4 + 0] * kk.x;
            s += q[d4 * 4 + 1] * kk.y;
            s += q[d4 * 4 + 2] * kk.z;
            s += q[d4 * 4 + 3] * kk.w;
        }
        float p = __expf(s * scale);   // logits ~O(1): safe without max-sub
        l += p;
        const float4* v4 = reinterpret_cast<const float4*>(&Vs[j][0]);
#pragma unroll
        for (int d4 = 0; d4 < DH / 4; ++d4) {
            float4 vv = v4[d4];
            acc[d4 * 4 + 0] += p * vv.x;
            acc[d4 * 4 + 1] += p * vv.y;
            acc[d4 * 4 + 2] += p * vv.z;
            acc[d4 * 4 + 3] += p * vv.w;
        }
    }

    float inv = 1.0f / l;
    float* dst = (b == 0)
        ? (final_in + ((size_t)(q0 + tid)) * CC + h * DH)
        : (attn_out + ((size_t)(b - 1) * HW + q0 + tid) * CC + h * DH);
#pragma unroll
    for (int d4 = 0; d4 < DH / 4; ++d4) {
        float4 o;
        o.x = acc[d4 * 4 + 0] * inv;
        o.y = acc[d4 * 4 + 1] * inv;
        o.z = acc[d4 * 4 + 2] * inv;
        o.w = acc[d4 * 4 + 3] * inv;
        *reinterpret_cast<float4*>(dst + d4 * 4) = o;
    }
}

// ---------------- weighted fusion of the 9 conditional attention outputs -----
__global__ __launch_bounds__(CC) void reduce_kernel(
    const float* __restrict__ attn, const float* __restrict__ pw,
    float* __restrict__ final_in, float* __restrict__ bscale)
{
    int pos = blockIdx.x;   // 0..4095
    int c = threadIdx.x;    // 0..319
    __shared__ float w[9];
    __shared__ float sinv;
    if (c < 9) w[c] = pw[(size_t)c * HW + pos];
    __syncthreads();
    if (c == 0) {
        float s = 0.0f;
        for (int i = 0; i < 9; i++) s += w[i];
        float iv = 1.0f / (s + 1e-6f);
        sinv = iv;
        bscale[pos] = s * iv;
    }
    __syncthreads();
    float accv = 0.0f;
#pragma unroll
    for (int i = 0; i < 9; i++)
        accv += w[i] * attn[((size_t)i * HW + pos) * CC + c];
    final_in[((size_t)(HW + pos)) * CC + c] = accv * sinv;
}

// ---------------- launch ------------------------------------------------------
extern "C" void kernel_launch(void* const* d_in, const int* in_sizes, int n_in,
                              void* d_out, int out_size)
{
    const float* hidden = (const float*)d_in[0];   // (2, 4096, 320)
    const float* ehs    = (const float*)d_in[1];   // (11, 77, 768)
    const float* bbox   = (const float*)d_in[2];   // (1, 8, 4)
    const float* Wq     = (const float*)d_in[3];
    const float* Wk     = (const float*)d_in[4];
    const float* Wv     = (const float*)d_in[5];
    const float* Wo     = (const float*)d_in[6];
    const float* bo     = (const float*)d_in[7];
    float* out = (float*)d_out;

    float *Qp, *Kp, *Vp, *Ap, *Fp, *Pp, *Bp;
    cudaGetSymbolAddress((void**)&Qp, g_Q);
    cudaGetSymbolAddress((void**)&Kp, g_K);
    cudaGetSymbolAddress((void**)&Vp, g_V);
    cudaGetSymbolAddress((void**)&Ap, g_attn);
    cudaGetSymbolAddress((void**)&Fp, g_final);
    cudaGetSymbolAddress((void**)&Pp, g_pw);
    cudaGetSymbolAddress((void**)&Bp, g_bscale);

    // Q projection on the 2 DISTINCT hidden states only (batches 1..9 share q)
    sgemm_kernel<<<dim3(CC / 64, (2 * HW) / 64), 256>>>(
        hidden, Wq, Qp, 2 * HW, CC, CC, nullptr, nullptr, 0);

    // K / V projections on ehs[:-1] = first 770 rows
    sgemm_kernel<<<dim3(CC / 64, (NBATCH * LKV + 63) / 64), 256>>>(
        ehs, Wk, Kp, NBATCH * LKV, CC, CX, nullptr, nullptr, 0);
    sgemm_kernel<<<dim3(CC / 64, (NBATCH * LKV + 63) / 64), 256>>>(
        ehs, Wv, Vp, NBATCH * LKV, CC, CX, nullptr, nullptr, 0);

    // phase weights from bboxes (separable antialiased resize)
    mask_kernel<<<64, 64>>>(bbox, Pp);

    // attention for 10 batches x 8 heads
    attn_kernel<<<dim3(HW / 128, NHEAD, NBATCH), 128>>>(Qp, Kp, Vp, Ap, Fp);

    // weighted fusion of conditional batches (Wo deferred; linearity)
    reduce_kernel<<<HW, CC>>>(Ap, Pp, Fp, Bp);

    // final projection of [attn_uncond ; fused] + bias
    sgemm_kernel<<<dim3(CC / 64, (2 * HW) / 64), 256>>>(
        Fp, Wo, out, 2 * HW, CC, CC, bo, Bp, 1);
}